// round 7
// baseline (speedup 1.0000x reference)
#include <cuda_runtime.h>

// ---------------------------------------------------------------------------
// MGPATH Sinkhorn-OT head, fused persistent kernel. R7:
// 8 rows/pass (halves txt LDS again), v-pair-packed f32x2 accumulators,
// single-slot 8-row prefetch, two 32-value butterflies per pass,
// 3 grid barriers total. Sinkhorn machinery identical to R6 (verified).
// ---------------------------------------------------------------------------

#define M_ROWS 65536
#define D_DIM  1024
#define NBLK   148
#define NTHR   448
#define NWARP  14
#define NGROUPS 2048            // 65536 rows / 32 rows-per-warp-group
#define NPASS  4                // 8 rows per pass
#define SINK_MAX_ITER 100
#define SINK_THRESH 0.01f

__device__ volatile float    g_part[2][NBLK * 16];
__device__ unsigned          g_cnt;
__device__ volatile unsigned g_gen;

__global__ void mg_init() { g_cnt = 0u; g_gen = 0u; }

// sense-reversing grid barrier; all NBLK blocks co-resident (1/SM, 148 SMs)
__device__ __forceinline__ void grid_barrier(unsigned &mygen) {
    __syncthreads();
    if (threadIdx.x == 0) {
        __threadfence();
        unsigned prev = atomicAdd(&g_cnt, 1u);
        if (prev == NBLK - 1) {
            g_cnt = 0u;
            __threadfence();
            g_gen = mygen + 1u;
        } else {
            while (g_gen == mygen) { __nanosleep(32); }
        }
        __threadfence();
    }
    __syncthreads();
    mygen++;
}

template <int NV>
__device__ __forceinline__ void block_reduce(float* vals, float* red) {
    #pragma unroll
    for (int i = 0; i < NV; i++) {
        #pragma unroll
        for (int o = 16; o > 0; o >>= 1)
            vals[i] += __shfl_down_sync(0xffffffffu, vals[i], o);
    }
    int w = threadIdx.x >> 5, l = threadIdx.x & 31;
    if (l == 0) {
        #pragma unroll
        for (int i = 0; i < NV; i++) red[i * 16 + w] = vals[i];
    }
    __syncthreads();
    if (threadIdx.x < 32) {
        #pragma unroll
        for (int i = 0; i < NV; i++) {
            float x = (l < NWARP) ? red[i * 16 + l] : 0.0f;
            #pragma unroll
            for (int o = 8; o > 0; o >>= 1)
                x += __shfl_down_sync(0xffffffffu, x, o);
            vals[i] = x;
        }
    }
    __syncthreads();
}

// 32-value 5-round multi-value butterfly (R6-verified): lane L ends with
// the fully-reduced value of index L.
__device__ __forceinline__ void butterfly32(float* vals, int lane) {
    #pragma unroll
    for (int h = 16; h >= 1; h >>= 1) {
        bool up = (lane & h) != 0;
        #pragma unroll
        for (int i = 0; i < h; i++) {
            float keep = up ? vals[i + h] : vals[i];
            float send = up ? vals[i]     : vals[i + h];
            vals[i] = keep + __shfl_xor_sync(0xffffffffu, send, h);
        }
    }
}

__global__ void __launch_bounds__(NTHR, 1)
mg_fused(const float* __restrict__ img,
         const float* __restrict__ txt,
         const float* __restrict__ ls,
         float* __restrict__ out) {
    // txtP float4 at index jj*256 + dd*64 + h*32 + lane:
    //   = { txt_v(4h+0)[d], txt_v(4h+1)[d], txt_v(4h+2)[d], txt_v(4h+3)[d] }
    //   with d = jj*128 + lane*4 + dd, txt_v(v)[d] = txt[((v&3)*2 + (v>>2))*D + d]
    __shared__ float4 txtP[2048];
    __shared__ float  simP[NWARP * 32];
    __shared__ float  red[9 * 16];
    __shared__ float  bc[9];

    const int tid  = threadIdx.x;
    const int lane = tid & 31;
    const int wid  = tid >> 5;

    for (int f = tid; f < 2048; f += NTHR) {
        int jj = f >> 8, rem = f & 255, u = rem >> 5, ln = rem & 31;
        int dd = u >> 1, h = u & 1;
        int d = jj * 128 + ln * 4 + dd;
        float4 val;
        val.x = txt[(0 * 2 + h) * D_DIM + d];   // n=0, c=h
        val.y = txt[(1 * 2 + h) * D_DIM + d];   // n=1
        val.z = txt[(2 * 2 + h) * D_DIM + d];   // n=2
        val.w = txt[(3 * 2 + h) * D_DIM + d];   // n=3
        txtP[f] = val;
    }
    __syncthreads();

    // round-robin: warp-slot wid*NBLK+blk owns one 32-row group
    const int rg = wid * NBLK + blockIdx.x;
    const bool active = (rg < NGROUPS);

    const ulonglong2* ts2 = reinterpret_cast<const ulonglong2*>(txtP);

    float simv[8] = {0.f, 0.f, 0.f, 0.f, 0.f, 0.f, 0.f, 0.f};

    if (active) {
        const float4* gp = reinterpret_cast<const float4*>(img)
                         + (size_t)rg * 32 * 256 + lane;

        // single 8-row prefetch slot over linear steps s = pass*8 + jj
        float4 buf[8];
        #pragma unroll
        for (int g = 0; g < 8; g++)
            buf[g] = __ldcs(gp + g * 256);           // step 0 (pass 0, jj 0)

        #pragma unroll 1
        for (int pass = 0; pass < NPASS; pass++) {
            unsigned long long acc[8][4];
            #pragma unroll
            for (int g = 0; g < 8; g++)
                #pragma unroll
                for (int vp = 0; vp < 4; vp++) acc[g][vp] = 0ull;

            #pragma unroll
            for (int jj = 0; jj < 8; jj++) {
                float4 c[8];
                #pragma unroll
                for (int g = 0; g < 8; g++) c[g] = buf[g];

                // refill slot with step s+1 (renamed copy -> no real MOVs)
                int s = pass * 8 + jj + 1;
                if (s < NPASS * 8) {
                    int tp = s >> 3, tj = s & 7;
                    #pragma unroll
                    for (int g = 0; g < 8; g++)
                        buf[g] = __ldcs(gp + (tp * 8 + g) * 256 + tj * 32);
                }

                #pragma unroll
                for (int dd = 0; dd < 4; dd++) {
                    ulonglong2 tvA = ts2[jj * 256 + dd * 64 + lane];       // v0..3
                    ulonglong2 tvB = ts2[jj * 256 + dd * 64 + 32 + lane];  // v4..7
                    #pragma unroll
                    for (int g = 0; g < 8; g++) {
                        float xv = (dd == 0) ? c[g].x : (dd == 1) ? c[g].y
                                 : (dd == 2) ? c[g].z : c[g].w;
                        unsigned long long xx;
                        asm("mov.b64 %0, {%1, %1};" : "=l"(xx) : "f"(xv));
                        asm("fma.rn.f32x2 %0, %1, %2, %0;" : "+l"(acc[g][0]) : "l"(xx), "l"(tvA.x));
                        asm("fma.rn.f32x2 %0, %1, %2, %0;" : "+l"(acc[g][1]) : "l"(xx), "l"(tvA.y));
                        asm("fma.rn.f32x2 %0, %1, %2, %0;" : "+l"(acc[g][2]) : "l"(xx), "l"(tvB.x));
                        asm("fma.rn.f32x2 %0, %1, %2, %0;" : "+l"(acc[g][3]) : "l"(xx), "l"(tvB.y));
                    }
                }
            }

            // ---- tree A: rows pass*8+0..3 (32 partials) ----
            {
                float vals[32];
                #pragma unroll
                for (int g = 0; g < 4; g++)
                    #pragma unroll
                    for (int vp = 0; vp < 4; vp++) {
                        float x, y;
                        asm("mov.b64 {%0, %1}, %2;" : "=f"(x), "=f"(y) : "l"(acc[g][vp]));
                        vals[g * 8 + vp * 2]     = x;
                        vals[g * 8 + vp * 2 + 1] = y;
                    }
                butterfly32(vals, lane);
                simP[wid * 32 + lane] = vals[0];
                __syncwarp();
                if ((lane >> 2) == 2 * pass) {
                    int base = wid * 32 + (lane & 3) * 8;
                    float4 s0 = *reinterpret_cast<float4*>(&simP[base]);
                    float4 s1 = *reinterpret_cast<float4*>(&simP[base + 4]);
                    simv[0] = s0.x; simv[1] = s0.y; simv[2] = s0.z; simv[3] = s0.w;
                    simv[4] = s1.x; simv[5] = s1.y; simv[6] = s1.z; simv[7] = s1.w;
                }
                __syncwarp();
            }
            // ---- tree B: rows pass*8+4..7 ----
            {
                float vals[32];
                #pragma unroll
                for (int g = 0; g < 4; g++)
                    #pragma unroll
                    for (int vp = 0; vp < 4; vp++) {
                        float x, y;
                        asm("mov.b64 {%0, %1}, %2;" : "=f"(x), "=f"(y) : "l"(acc[g + 4][vp]));
                        vals[g * 8 + vp * 2]     = x;
                        vals[g * 8 + vp * 2 + 1] = y;
                    }
                butterfly32(vals, lane);
                simP[wid * 32 + lane] = vals[0];
                __syncwarp();
                if ((lane >> 2) == 2 * pass + 1) {
                    int base = wid * 32 + (lane & 3) * 8;
                    float4 s0 = *reinterpret_cast<float4*>(&simP[base]);
                    float4 s1 = *reinterpret_cast<float4*>(&simP[base + 4]);
                    simv[0] = s0.x; simv[1] = s0.y; simv[2] = s0.z; simv[3] = s0.w;
                    simv[4] = s1.x; simv[5] = s1.y; simv[6] = s1.z; simv[7] = s1.w;
                }
                __syncwarp();
            }
        }
    }

    // K = exp(-(1 - sim)/0.1); lane owns row rg*32 + lane
    float Kv[8];
    #pragma unroll
    for (int i = 0; i < 8; i++) Kv[i] = active ? expf((simv[i] - 1.0f) * 10.0f) : 0.0f;

    const float uu = 1.0f / (float)M_ROWS;
    float cm[8], cp[8];
    #pragma unroll
    for (int i = 0; i < 8; i++) { cm[i] = 1.0f; cp[i] = 1.0f; }

    // ---- Sinkhorn loop: 1 grid barrier per iteration (parity slabs,
    //      every block redundantly reduces all partials) ----
    unsigned mygen = 0;
    int t = 0;
    for (;;) {
        t++;
        float vals9[9];
        if (active) {
            float err = 0.0f;
            float rr[2];
            #pragma unroll
            for (int b = 0; b < 2; b++) {
                float s = 0.0f, s2 = 0.0f;
                #pragma unroll
                for (int n = 0; n < 4; n++) {
                    s  = fmaf(Kv[b * 4 + n], cm[b * 4 + n], s);
                    s2 = fmaf(Kv[b * 4 + n], cp[b * 4 + n], s2);
                }
                float r    = uu / s;
                float rold = (t == 1) ? 1.0f : uu / s2;   // r0 = ones
                rr[b] = r;
                err += fabsf(r - rold);
            }
            #pragma unroll
            for (int b = 0; b < 2; b++)
                #pragma unroll
                for (int n = 0; n < 4; n++)
                    vals9[b * 4 + n] = Kv[b * 4 + n] * rr[b];
            vals9[8] = err;
        } else {
            #pragma unroll
            for (int i = 0; i < 9; i++) vals9[i] = 0.0f;
        }

        block_reduce<9>(vals9, red);
        const int sl = t & 1;
        if (tid == 0) {
            #pragma unroll
            for (int i = 0; i < 9; i++) g_part[sl][blockIdx.x * 16 + i] = vals9[i];
        }
        grid_barrier(mygen);

        // every block reduces all partials (identical result everywhere)
        float pv[9];
        #pragma unroll
        for (int i = 0; i < 9; i++)
            pv[i] = (tid < NBLK) ? g_part[sl][tid * 16 + i] : 0.0f;
        block_reduce<9>(pv, red);
        if (tid == 0) {
            float e = pv[8] * (1.0f / (2.0f * (float)M_ROWS));
            #pragma unroll
            for (int i = 0; i < 8; i++) bc[i] = 0.25f / pv[i];   // v = 1/N
            bc[8] = (e < SINK_THRESH || t >= SINK_MAX_ITER) ? 1.0f : 0.0f;
        }
        __syncthreads();
        int stop = (bc[8] != 0.0f);
        #pragma unroll
        for (int i = 0; i < 8; i++) { cp[i] = cm[i]; cm[i] = bc[i]; }
        if (stop) break;
    }

    // ---- final: sim_op[b] = sum_m r_T[m] * sum_n c_T[n] K[m,n] sim[m,n] ----
    float ov[2] = {0.0f, 0.0f};
    if (active) {
        #pragma unroll
        for (int b = 0; b < 2; b++) {
            float s = 0.0f, a = 0.0f;
            #pragma unroll
            for (int n = 0; n < 4; n++) {
                s = fmaf(Kv[b * 4 + n], cp[b * 4 + n], s);
                a = fmaf(cm[b * 4 + n] * Kv[b * 4 + n], simv[b * 4 + n], a);
            }
            ov[b] = (uu / s) * a;
        }
    }
    block_reduce<2>(ov, red);
    const int slf = (t + 1) & 1;
    if (tid == 0) {
        g_part[slf][blockIdx.x * 16 + 0] = ov[0];
        g_part[slf][blockIdx.x * 16 + 1] = ov[1];
    }
    grid_barrier(mygen);
    if (blockIdx.x == 0) {
        float pv[2];
        pv[0] = (tid < NBLK) ? g_part[slf][tid * 16 + 0] : 0.0f;
        pv[1] = (tid < NBLK) ? g_part[slf][tid * 16 + 1] : 0.0f;
        block_reduce<2>(pv, red);
        if (tid == 0) {
            float sc = expf(ls[0]);
            out[0] = sc * pv[0];
            out[1] = sc * pv[1];
        }
    }
}

extern "C" void kernel_launch(void* const* d_in, const int* in_sizes, int n_in,
                              void* d_out, int out_size) {
    const float* img = (const float*)d_in[0];
    const float* txt = (const float*)d_in[1];
    const float* ls  = (const float*)d_in[2];
    float* out = (float*)d_out;
    (void)in_sizes; (void)n_in; (void)out_size;

    mg_init<<<1, 1>>>();
    mg_fused<<<NBLK, NTHR>>>(img, txt, ls, out);
}

// round 8
// speedup vs baseline: 1.1198x; 1.1198x over previous
#include <cuda_runtime.h>

// ---------------------------------------------------------------------------
// MGPATH Sinkhorn-OT head, fused persistent kernel. R8:
// 7 warps x 2 groups/warp (98.8% util, 292 regs/thread -> no spills),
// 8 rows/pass v-pair-packed f32x2 GEMM (R7-verified math), depth-2
// double-buffer prefetch, 3 grid barriers. Sinkhorn machinery R6-verified.
// ---------------------------------------------------------------------------

#define M_ROWS 65536
#define D_DIM  1024
#define NBLK   148
#define NTHR   224
#define NWARP  7
#define NSLOTS (NWARP * NBLK)   // 1036
#define NGROUPS 2048            // 65536 rows / 32 rows-per-group
#define NPASS  4                // 8 rows per pass
#define SINK_MAX_ITER 100
#define SINK_THRESH 0.01f

__device__ volatile float    g_part[2][NBLK * 16];
__device__ unsigned          g_cnt;
__device__ volatile unsigned g_gen;

__global__ void mg_init() { g_cnt = 0u; g_gen = 0u; }

// sense-reversing grid barrier; all NBLK blocks co-resident (1/SM, 148 SMs)
__device__ __forceinline__ void grid_barrier(unsigned &mygen) {
    __syncthreads();
    if (threadIdx.x == 0) {
        __threadfence();
        unsigned prev = atomicAdd(&g_cnt, 1u);
        if (prev == NBLK - 1) {
            g_cnt = 0u;
            __threadfence();
            g_gen = mygen + 1u;
        } else {
            while (g_gen == mygen) { __nanosleep(32); }
        }
        __threadfence();
    }
    __syncthreads();
    mygen++;
}

template <int NV>
__device__ __forceinline__ void block_reduce(float* vals, float* red) {
    #pragma unroll
    for (int i = 0; i < NV; i++) {
        #pragma unroll
        for (int o = 16; o > 0; o >>= 1)
            vals[i] += __shfl_down_sync(0xffffffffu, vals[i], o);
    }
    int w = threadIdx.x >> 5, l = threadIdx.x & 31;
    if (l == 0) {
        #pragma unroll
        for (int i = 0; i < NV; i++) red[i * 16 + w] = vals[i];
    }
    __syncthreads();
    if (threadIdx.x < 32) {
        #pragma unroll
        for (int i = 0; i < NV; i++) {
            float x = (l < NWARP) ? red[i * 16 + l] : 0.0f;
            #pragma unroll
            for (int o = 8; o > 0; o >>= 1)
                x += __shfl_down_sync(0xffffffffu, x, o);
            vals[i] = x;
        }
    }
    __syncthreads();
}

// 32-value 5-round multi-value butterfly (R6/R7-verified): lane L ends with
// the fully-reduced value of index L.
__device__ __forceinline__ void butterfly32(float* vals, int lane) {
    #pragma unroll
    for (int h = 16; h >= 1; h >>= 1) {
        bool up = (lane & h) != 0;
        #pragma unroll
        for (int i = 0; i < h; i++) {
            float keep = up ? vals[i + h] : vals[i];
            float send = up ? vals[i]     : vals[i + h];
            vals[i] = keep + __shfl_xor_sync(0xffffffffu, send, h);
        }
    }
}

__global__ void __launch_bounds__(NTHR, 1)
mg_fused(const float* __restrict__ img,
         const float* __restrict__ txt,
         const float* __restrict__ ls,
         float* __restrict__ out) {
    // txtP float4 at index jj*256 + dd*64 + h*32 + lane:
    //   = { txt_v(4h+0)[d], txt_v(4h+1)[d], txt_v(4h+2)[d], txt_v(4h+3)[d] }
    //   with d = jj*128 + lane*4 + dd, txt_v(v)[d] = txt[((v&3)*2 + (v>>2))*D + d]
    __shared__ float4 txtP[2048];
    __shared__ float  simP[NWARP * 32];
    __shared__ float  red[9 * 16];
    __shared__ float  bc[9];

    const int tid  = threadIdx.x;
    const int lane = tid & 31;
    const int wid  = tid >> 5;

    for (int f = tid; f < 2048; f += NTHR) {
        int jj = f >> 8, rem = f & 255, u = rem >> 5, ln = rem & 31;
        int dd = u >> 1, h = u & 1;
        int d = jj * 128 + ln * 4 + dd;
        float4 val;
        val.x = txt[(0 * 2 + h) * D_DIM + d];   // n=0, c=h
        val.y = txt[(1 * 2 + h) * D_DIM + d];   // n=1
        val.z = txt[(2 * 2 + h) * D_DIM + d];   // n=2
        val.w = txt[(3 * 2 + h) * D_DIM + d];   // n=3
        txtP[f] = val;
    }
    __syncthreads();

    // warp-slot owns groups gslot and gslot+NSLOTS (round-robin, 2 max)
    const int gslot = wid * NBLK + blockIdx.x;          // < 1036 < 2048
    const bool has1 = (gslot + NSLOTS < NGROUPS);

    const ulonglong2* ts2 = reinterpret_cast<const ulonglong2*>(txtP);

    float simv[2][8];
    #pragma unroll
    for (int q = 0; q < 2; q++)
        #pragma unroll
        for (int v = 0; v < 8; v++) simv[q][v] = 0.0f;

    #pragma unroll 1
    for (int q = 0; q < 2; q++) {
        const int rg = gslot + q * NSLOTS;
        if (q == 1 && !has1) break;

        const float4* gp = reinterpret_cast<const float4*>(img)
                         + (size_t)rg * 32 * 256 + lane;

        // depth-2 double buffer over linear steps s = pass*8 + jj (8 rows)
        float4 buf[2][8];
        #pragma unroll
        for (int g = 0; g < 8; g++) buf[0][g] = __ldcs(gp + g * 256);
        #pragma unroll
        for (int g = 0; g < 8; g++) buf[1][g] = __ldcs(gp + g * 256 + 32);

        #pragma unroll 1
        for (int pass = 0; pass < NPASS; pass++) {
            unsigned long long acc[8][4];
            #pragma unroll
            for (int g = 0; g < 8; g++)
                #pragma unroll
                for (int vp = 0; vp < 4; vp++) acc[g][vp] = 0ull;

            #pragma unroll
            for (int jj = 0; jj < 8; jj++) {
                const int p = jj & 1;
                float4 c[8];
                #pragma unroll
                for (int g = 0; g < 8; g++) c[g] = buf[p][g];

                // refill this parity slot with step s+2
                int s = pass * 8 + jj + 2;
                if (s < NPASS * 8) {
                    int tp = s >> 3, tj = s & 7;
                    #pragma unroll
                    for (int g = 0; g < 8; g++)
                        buf[p][g] = __ldcs(gp + (tp * 8 + g) * 256 + tj * 32);
                }

                #pragma unroll
                for (int dd = 0; dd < 4; dd++) {
                    ulonglong2 tvA = ts2[jj * 256 + dd * 64 + lane];       // v0..3
                    ulonglong2 tvB = ts2[jj * 256 + dd * 64 + 32 + lane];  // v4..7
                    #pragma unroll
                    for (int g = 0; g < 8; g++) {
                        float xv = (dd == 0) ? c[g].x : (dd == 1) ? c[g].y
                                 : (dd == 2) ? c[g].z : c[g].w;
                        unsigned long long xx;
                        asm("mov.b64 %0, {%1, %1};" : "=l"(xx) : "f"(xv));
                        asm("fma.rn.f32x2 %0, %1, %2, %0;" : "+l"(acc[g][0]) : "l"(xx), "l"(tvA.x));
                        asm("fma.rn.f32x2 %0, %1, %2, %0;" : "+l"(acc[g][1]) : "l"(xx), "l"(tvA.y));
                        asm("fma.rn.f32x2 %0, %1, %2, %0;" : "+l"(acc[g][2]) : "l"(xx), "l"(tvB.x));
                        asm("fma.rn.f32x2 %0, %1, %2, %0;" : "+l"(acc[g][3]) : "l"(xx), "l"(tvB.y));
                    }
                }
            }

            // ---- tree A: rows pass*8+0..3 (32 partials) ----
            {
                float vals[32];
                #pragma unroll
                for (int g = 0; g < 4; g++)
                    #pragma unroll
                    for (int vp = 0; vp < 4; vp++) {
                        float x, y;
                        asm("mov.b64 {%0, %1}, %2;" : "=f"(x), "=f"(y) : "l"(acc[g][vp]));
                        vals[g * 8 + vp * 2]     = x;
                        vals[g * 8 + vp * 2 + 1] = y;
                    }
                butterfly32(vals, lane);
                simP[wid * 32 + lane] = vals[0];
                __syncwarp();
                if ((lane >> 2) == 2 * pass) {
                    int base = wid * 32 + (lane & 3) * 8;
                    float4 s0 = *reinterpret_cast<float4*>(&simP[base]);
                    float4 s1 = *reinterpret_cast<float4*>(&simP[base + 4]);
                    simv[q][0] = s0.x; simv[q][1] = s0.y; simv[q][2] = s0.z; simv[q][3] = s0.w;
                    simv[q][4] = s1.x; simv[q][5] = s1.y; simv[q][6] = s1.z; simv[q][7] = s1.w;
                }
                __syncwarp();
            }
            // ---- tree B: rows pass*8+4..7 ----
            {
                float vals[32];
                #pragma unroll
                for (int g = 0; g < 4; g++)
                    #pragma unroll
                    for (int vp = 0; vp < 4; vp++) {
                        float x, y;
                        asm("mov.b64 {%0, %1}, %2;" : "=f"(x), "=f"(y) : "l"(acc[g + 4][vp]));
                        vals[g * 8 + vp * 2]     = x;
                        vals[g * 8 + vp * 2 + 1] = y;
                    }
                butterfly32(vals, lane);
                simP[wid * 32 + lane] = vals[0];
                __syncwarp();
                if ((lane >> 2) == 2 * pass + 1) {
                    int base = wid * 32 + (lane & 3) * 8;
                    float4 s0 = *reinterpret_cast<float4*>(&simP[base]);
                    float4 s1 = *reinterpret_cast<float4*>(&simP[base + 4]);
                    simv[q][0] = s0.x; simv[q][1] = s0.y; simv[q][2] = s0.z; simv[q][3] = s0.w;
                    simv[q][4] = s1.x; simv[q][5] = s1.y; simv[q][6] = s1.z; simv[q][7] = s1.w;
                }
                __syncwarp();
            }
        }
    }

    // K = exp(-(1 - sim)/0.1); lane owns rows gslot*32+lane (+ NSLOTS*32)
    float Kv[2][8];
    #pragma unroll
    for (int i = 0; i < 8; i++) {
        Kv[0][i] = expf((simv[0][i] - 1.0f) * 10.0f);
        Kv[1][i] = has1 ? expf((simv[1][i] - 1.0f) * 10.0f) : 0.0f;
    }

    const float uu = 1.0f / (float)M_ROWS;
    float cm[8], cp[8];
    #pragma unroll
    for (int i = 0; i < 8; i++) { cm[i] = 1.0f; cp[i] = 1.0f; }

    // ---- Sinkhorn loop: 1 grid barrier per iteration (parity slabs,
    //      every block redundantly reduces all partials) ----
    unsigned mygen = 0;
    int t = 0;
    for (;;) {
        t++;
        float vals9[9];
        #pragma unroll
        for (int i = 0; i < 9; i++) vals9[i] = 0.0f;

        #pragma unroll
        for (int q = 0; q < 2; q++) {
            if (q == 1 && !has1) break;
            #pragma unroll
            for (int b = 0; b < 2; b++) {
                float s = 0.0f, s2 = 0.0f;
                #pragma unroll
                for (int n = 0; n < 4; n++) {
                    s  = fmaf(Kv[q][b * 4 + n], cm[b * 4 + n], s);
                    s2 = fmaf(Kv[q][b * 4 + n], cp[b * 4 + n], s2);
                }
                float r    = uu / s;
                float rold = (t == 1) ? 1.0f : uu / s2;   // r0 = ones
                vals9[8] += fabsf(r - rold);
                #pragma unroll
                for (int n = 0; n < 4; n++)
                    vals9[b * 4 + n] += Kv[q][b * 4 + n] * r;
            }
        }

        block_reduce<9>(vals9, red);
        const int sl = t & 1;
        if (tid == 0) {
            #pragma unroll
            for (int i = 0; i < 9; i++) g_part[sl][blockIdx.x * 16 + i] = vals9[i];
        }
        grid_barrier(mygen);

        // every block reduces all partials (identical result everywhere)
        float pv[9];
        #pragma unroll
        for (int i = 0; i < 9; i++)
            pv[i] = (tid < NBLK) ? g_part[sl][tid * 16 + i] : 0.0f;
        block_reduce<9>(pv, red);
        if (tid == 0) {
            float e = pv[8] * (1.0f / (2.0f * (float)M_ROWS));
            #pragma unroll
            for (int i = 0; i < 8; i++) bc[i] = 0.25f / pv[i];   // v = 1/N
            bc[8] = (e < SINK_THRESH || t >= SINK_MAX_ITER) ? 1.0f : 0.0f;
        }
        __syncthreads();
        int stop = (bc[8] != 0.0f);
        #pragma unroll
        for (int i = 0; i < 8; i++) { cp[i] = cm[i]; cm[i] = bc[i]; }
        if (stop) break;
    }

    // ---- final: sim_op[b] = sum_m r_T[m] * sum_n c_T[n] K[m,n] sim[m,n] ----
    float ov[2] = {0.0f, 0.0f};
    #pragma unroll
    for (int q = 0; q < 2; q++) {
        if (q == 1 && !has1) break;
        #pragma unroll
        for (int b = 0; b < 2; b++) {
            float s = 0.0f, a = 0.0f;
            #pragma unroll
            for (int n = 0; n < 4; n++) {
                s = fmaf(Kv[q][b * 4 + n], cp[b * 4 + n], s);
                a = fmaf(cm[b * 4 + n] * Kv[q][b * 4 + n], simv[q][b * 4 + n], a);
            }
            ov[b] += (uu / s) * a;
        }
    }
    block_reduce<2>(ov, red);
    const int slf = (t + 1) & 1;
    if (tid == 0) {
        g_part[slf][blockIdx.x * 16 + 0] = ov[0];
        g_part[slf][blockIdx.x * 16 + 1] = ov[1];
    }
    grid_barrier(mygen);
    if (blockIdx.x == 0) {
        float pv[2];
        pv[0] = (tid < NBLK) ? g_part[slf][tid * 16 + 0] : 0.0f;
        pv[1] = (tid < NBLK) ? g_part[slf][tid * 16 + 1] : 0.0f;
        block_reduce<2>(pv, red);
        if (tid == 0) {
            float sc = expf(ls[0]);
            out[0] = sc * pv[0];
            out[1] = sc * pv[1];
        }
    }
}

extern "C" void kernel_launch(void* const* d_in, const int* in_sizes, int n_in,
                              void* d_out, int out_size) {
    const float* img = (const float*)d_in[0];
    const float* txt = (const float*)d_in[1];
    const float* ls  = (const float*)d_in[2];
    float* out = (float*)d_out;
    (void)in_sizes; (void)n_in; (void)out_size;

    mg_init<<<1, 1>>>();
    mg_fused<<<NBLK, NTHR>>>(img, txt, ls, out);
}